// round 13
// baseline (speedup 1.0000x reference)
#include <cuda_runtime.h>
#include <cuda_fp16.h>
#include <cstdint>

// ---------------- scratch (no cudaMalloc allowed) ----------------
__device__ __half g_h1h[256 * 1024 * 8];   // LSTM1 outputs as fp16, [B][S][8], 4MB

// ---------------- fast activations: MUFU.TANH based ----------------
__device__ __forceinline__ float tanhapx(float x) {
    float r; asm("tanh.approx.f32 %0, %1;" : "=f"(r) : "f"(x)); return r;
}
__device__ __forceinline__ __half2 u2h(unsigned u) {
    return *reinterpret_cast<__half2*>(&u);
}

// =================================================================
// Kernel 1: LSTM1. One thread per (b,s) sequence: 16 steps, input=1, H=8.
// =================================================================
__device__ __forceinline__ void lstm_upd(float& c, float& h,
                                         float gi, float gf, float gg, float go) {
    float ti = tanhapx(0.5f * gi);
    float tf = tanhapx(0.5f * gf);
    float tg = tanhapx(gg);
    float to = tanhapx(0.5f * go);
    float p  = fmaf(0.5f * ti, tg, 0.5f * tg);          // sig(i)*tanh(g)
    c = fmaf(0.5f * tf, c, fmaf(0.5f, c, p));           // sig(f)*c + p
    float tc = tanhapx(c);
    h = fmaf(0.5f * to, tc, 0.5f * tc);                 // sig(o)*tanh(c)
}

__global__ __launch_bounds__(256) void lstm1_kernel(
    const float* __restrict__ x,
    const float* __restrict__ W_ih1, const float* __restrict__ W_hh1,
    const float* __restrict__ b_ih1, const float* __restrict__ b_hh1)
{
    __shared__ float sI[32];          // W_ih per gate
    __shared__ float sB[32];          // fused bias per gate
    __shared__ float sT[8][32];       // sT[e][gate] = W_hh1[gate][e]
    int tid = threadIdx.x;
    if (tid < 32) { sI[tid] = W_ih1[tid]; sB[tid] = b_ih1[tid] + b_hh1[tid]; }
    sT[tid & 7][tid >> 3] = W_hh1[tid];
    __syncthreads();

    long n = (long)blockIdx.x * 256 + tid;
    const float4* xp = (const float4*)(x + n * 16);
    float4 xq[4];
    xq[0] = xp[0]; xq[1] = xp[1]; xq[2] = xp[2]; xq[3] = xp[3];
    float xv[16];
#pragma unroll
    for (int i = 0; i < 4; i++) {
        xv[4 * i + 0] = xq[i].x; xv[4 * i + 1] = xq[i].y;
        xv[4 * i + 2] = xq[i].z; xv[4 * i + 3] = xq[i].w;
    }

    float h[8], c[8];
#pragma unroll
    for (int d = 0; d < 8; d++) { h[d] = 0.f; c[d] = 0.f; }

    const float4* I4 = (const float4*)sI;
    const float4* B4 = (const float4*)sB;

#pragma unroll
    for (int t = 0; t < 16; t++) {
        float xt = xv[t];
        float4 acc[8];
#pragma unroll
        for (int q = 0; q < 8; q++) {
            float4 w = I4[q], bb = B4[q];
            acc[q].x = fmaf(w.x, xt, bb.x);
            acc[q].y = fmaf(w.y, xt, bb.y);
            acc[q].z = fmaf(w.z, xt, bb.z);
            acc[q].w = fmaf(w.w, xt, bb.w);
        }
#pragma unroll
        for (int e = 0; e < 8; e++) {
            float he = h[e];
            const float4* T4 = (const float4*)sT[e];
#pragma unroll
            for (int q = 0; q < 8; q++) {
                float4 w = T4[q];
                acc[q].x = fmaf(w.x, he, acc[q].x);
                acc[q].y = fmaf(w.y, he, acc[q].y);
                acc[q].z = fmaf(w.z, he, acc[q].z);
                acc[q].w = fmaf(w.w, he, acc[q].w);
            }
        }
#pragma unroll
        for (int q = 0; q < 2; q++) {   // i=acc[0..1], f=[2..3], g=[4..5], o=[6..7]
            float4 ai = acc[q], af = acc[2 + q], ag = acc[4 + q], ao = acc[6 + q];
            lstm_upd(c[4 * q + 0], h[4 * q + 0], ai.x, af.x, ag.x, ao.x);
            lstm_upd(c[4 * q + 1], h[4 * q + 1], ai.y, af.y, ag.y, ao.y);
            lstm_upd(c[4 * q + 2], h[4 * q + 2], ai.z, af.z, ag.z, ao.z);
            lstm_upd(c[4 * q + 3], h[4 * q + 3], ai.w, af.w, ag.w, ao.w);
        }
    }

    __half2 p0 = __floats2half2_rn(h[0], h[1]);
    __half2 p1 = __floats2half2_rn(h[2], h[3]);
    __half2 p2 = __floats2half2_rn(h[4], h[5]);
    __half2 p3 = __floats2half2_rn(h[6], h[7]);
    uint4 u;
    u.x = *reinterpret_cast<uint32_t*>(&p0);
    u.y = *reinterpret_cast<uint32_t*>(&p1);
    u.z = *reinterpret_cast<uint32_t*>(&p2);
    u.w = *reinterpret_cast<uint32_t*>(&p3);
    *reinterpret_cast<uint4*>(g_h1h + n * 8) = u;
}

// =================================================================
// Kernel 2: LSTM2, persistent, 128 CTAs x 512 threads, 2 batches/CTA.
// FUSED design, ONE barrier per step:
//   thread t: gate g = t&3 (i,f,g,o), unit d = t>>2, row j = g*128+d.
//   Phase A (unchanged math): 68 half2 weight regs, HFMA2 chains, fp32
//   accumulators (a0, a1) for batches 0/1.
//   Then 8 __shfl_sync gather the 4 gates of unit d (both batches) within
//   the 4-lane group; each thread updates cell (d, b = g&1) [2x redundant].
//   Gate-0/1 lanes write h_{s+1}; gate-2, d<16 lanes stage x_{s+1}.
//   vec is DOUBLE-BUFFERED by step parity -> no read/write race with a
//   single __syncthreads per step.
// =================================================================
__global__ void __launch_bounds__(512, 1) lstm2_kernel(
    const float* __restrict__ W_ih2, const float* __restrict__ W_hh2,
    const float* __restrict__ b_ih2, const float* __restrict__ b_hh2,
    const float* __restrict__ W1, const float* __restrict__ b1,
    const float* __restrict__ W2, const float* __restrict__ b2,
    float* __restrict__ out)
{
    __shared__ __half2 vecH[2][2][80];   // [parity][batch][k-pair], 68 used
    __shared__ float   hb[256];
    __shared__ float   red[8];

    const int t    = threadIdx.x;
    const int gate = t & 3;              // 0=i, 1=f, 2=g, 3=o
    const int d    = t >> 2;             // 0..127
    const int j    = gate * 128 + d;     // gate row
    const int b0   = blockIdx.x * 2;

    // ---- pack this row's weights into 68 half2 registers ----
    __half2 wreg[68];
    {
        const float4* wi4 = (const float4*)(W_ih2 + j * 8);
#pragma unroll
        for (int q = 0; q < 2; q++) {
            float4 v = wi4[q];
            wreg[2 * q + 0] = __floats2half2_rn(v.x, v.y);
            wreg[2 * q + 1] = __floats2half2_rn(v.z, v.w);
        }
        const float4* wh4 = (const float4*)(W_hh2 + j * 128);
#pragma unroll
        for (int q = 0; q < 32; q++) {
            float4 v = wh4[q];
            wreg[4 + 2 * q + 0] = __floats2half2_rn(v.x, v.y);
            wreg[4 + 2 * q + 1] = __floats2half2_rn(v.z, v.w);
        }
    }
    const float bias = b_ih2[j] + b_hh2[j];

    // ---- init both buffers to zero; stage x_0 into buffer 0 ----
    if (t < 320) ((float*)vecH)[t] = 0.f;
    __syncthreads();
    __half xr = __float2half_rn(0.f);    // x prefetch (gate==2, d<16 lanes)
    if (gate == 2 && d < 16) {
        int b = d >> 3, k = d & 7;
        ((__half*)vecH[0][b])[k] = g_h1h[((long)(b0 + b) * 1024 + 0) * 8 + k];
        xr = g_h1h[((long)(b0 + b) * 1024 + 1) * 8 + k];
    }
    float c_ = 0.f, h_ = 0.f;            // state for (d, b = gate&1)
    __syncthreads();

    const int lb = (t & 31) & ~3;        // base lane of 4-lane group
    const int myb = gate & 1;            // which batch this thread updates
    const __half2 hz = __float2half2_rn(0.f);

#pragma unroll 2
    for (int step = 0; step < 1024; step++) {
        const int p = step & 1;
        const uint4* V0 = (const uint4*)(vecH[p][0]);   // uint4 = 8 k
        const uint4* V1 = (const uint4*)(vecH[p][1]);

        // ---- phase A: full-row dot products, 2 batches ----
        float a0 = bias, a1 = bias;
#pragma unroll
        for (int blk = 0; blk < 4; blk++) {       // q = 4*blk .. 4*blk+3 (32 k)
            __half2 sA0 = hz, sB0 = hz, sA1 = hz, sB1 = hz;
#pragma unroll
            for (int qq = 0; qq < 4; qq++) {
                int q = blk * 4 + qq;
                uint4 u0 = V0[q];
                uint4 u1 = V1[q];
                __half2 w0 = wreg[4 * q + 0], w1 = wreg[4 * q + 1];
                __half2 w2 = wreg[4 * q + 2], w3 = wreg[4 * q + 3];
                sA0 = __hfma2(w0, u2h(u0.x), sA0);
                sB0 = __hfma2(w1, u2h(u0.y), sB0);
                sA0 = __hfma2(w2, u2h(u0.z), sA0);
                sB0 = __hfma2(w3, u2h(u0.w), sB0);
                sA1 = __hfma2(w0, u2h(u1.x), sA1);
                sB1 = __hfma2(w1, u2h(u1.y), sB1);
                sA1 = __hfma2(w2, u2h(u1.z), sA1);
                sB1 = __hfma2(w3, u2h(u1.w), sB1);
            }
            float2 f0 = __half22float2(__hadd2(sA0, sB0));
            float2 f1 = __half22float2(__hadd2(sA1, sB1));
            a0 += f0.x; a0 += f0.y;
            a1 += f1.x; a1 += f1.y;
        }
        {   // tail: q = 16 (k 128..135)
            uint4 u0 = V0[16];
            uint4 u1 = V1[16];
            __half2 w0 = wreg[64], w1 = wreg[65], w2 = wreg[66], w3 = wreg[67];
            __half2 sA0 = __hfma2(w0, u2h(u0.x), hz);
            __half2 sB0 = __hfma2(w1, u2h(u0.y), hz);
            sA0 = __hfma2(w2, u2h(u0.z), sA0);
            sB0 = __hfma2(w3, u2h(u0.w), sB0);
            __half2 sA1 = __hfma2(w0, u2h(u1.x), hz);
            __half2 sB1 = __hfma2(w1, u2h(u1.y), hz);
            sA1 = __hfma2(w2, u2h(u1.z), sA1);
            sB1 = __hfma2(w3, u2h(u1.w), sB1);
            float2 f0 = __half22float2(__hadd2(sA0, sB0));
            float2 f1 = __half22float2(__hadd2(sA1, sB1));
            a0 += f0.x; a0 += f0.y;
            a1 += f1.x; a1 += f1.y;
        }

        // ---- shuffle: gather 4 gates of unit d, both batches ----
        const unsigned m = 0xffffffffu;
        float i0 = __shfl_sync(m, a0, lb + 0);
        float f0s = __shfl_sync(m, a0, lb + 1);
        float g0 = __shfl_sync(m, a0, lb + 2);
        float o0 = __shfl_sync(m, a0, lb + 3);
        float i1 = __shfl_sync(m, a1, lb + 0);
        float f1s = __shfl_sync(m, a1, lb + 1);
        float g1 = __shfl_sync(m, a1, lb + 2);
        float o1 = __shfl_sync(m, a1, lb + 3);

        // ---- activation for (d, myb) ----
        float gi = myb ? i1 : i0;
        float gf = myb ? f1s : f0s;
        float gg = myb ? g1 : g0;
        float go = myb ? o1 : o0;
        float ti = tanhapx(0.5f * gi);
        float tf = tanhapx(0.5f * gf);
        float tg = tanhapx(gg);
        float to = tanhapx(0.5f * go);
        float pq = fmaf(0.5f * ti, tg, 0.5f * tg);
        c_ = fmaf(0.5f * tf, c_, fmaf(0.5f, c_, pq));
        float tc = tanhapx(c_);
        h_ = fmaf(0.5f * to, tc, 0.5f * tc);

        // ---- write h_{s+1} / x_{s+1} into the OTHER buffer ----
        if (gate < 2) {
            ((__half*)vecH[p ^ 1][myb])[8 + d] = __float2half_rn(h_);
        } else if (gate == 2 && d < 16) {
            int b = d >> 3, k = d & 7;
            ((__half*)vecH[p ^ 1][b])[k] = xr;        // x_{step+1}
            if (step + 2 < 1024)
                xr = g_h1h[((long)(b0 + b) * 1024 + step + 2) * 8 + k];
        }
        __syncthreads();
    }

    // ---- epilogue: out[b] = (h @ W1^T + b1) @ W2^T + b2 ----
    if (gate == 0) hb[d] = h_;            // batch 0
    if (gate == 1) hb[128 + d] = h_;      // batch 1
    __syncthreads();
    if (t < 128) {
        int b = t >> 6, jj = t & 63;
        const float* hv  = hb + b * 128;
        const float* w1r = W1 + jj * 128;
        float m_ = b1[jj];
#pragma unroll
        for (int k = 0; k < 128; k++) m_ = fmaf(w1r[k], hv[k], m_);
        float pr = m_ * W2[jj];
#pragma unroll
        for (int off = 16; off; off >>= 1)
            pr += __shfl_xor_sync(0xffffffff, pr, off);
        if ((t & 31) == 0) red[t >> 5] = pr;
    }
    __syncthreads();
    if (t < 2)
        out[b0 + t] = red[t * 2] + red[t * 2 + 1] + b2[0];
}

// =================================================================
extern "C" void kernel_launch(void* const* d_in, const int* in_sizes, int n_in,
                              void* d_out, int out_size) {
    const float* x     = (const float*)d_in[0];
    // d_in[1] = data (unused)
    const float* W_ih1 = (const float*)d_in[2];
    const float* W_hh1 = (const float*)d_in[3];
    const float* b_ih1 = (const float*)d_in[4];
    const float* b_hh1 = (const float*)d_in[5];
    const float* W_ih2 = (const float*)d_in[6];
    const float* W_hh2 = (const float*)d_in[7];
    const float* b_ih2 = (const float*)d_in[8];
    const float* b_hh2 = (const float*)d_in[9];
    const float* W1    = (const float*)d_in[10];
    const float* b1    = (const float*)d_in[11];
    const float* W2    = (const float*)d_in[12];
    const float* b2    = (const float*)d_in[13];
    float* out = (float*)d_out;

    lstm1_kernel<<<1024, 256>>>(x, W_ih1, W_hh1, b_ih1, b_hh1);

    lstm2_kernel<<<128, 512>>>(W_ih2, W_hh2, b_ih2, b_hh2,
                               W1, b1, W2, b2, out);
}

// round 16
// speedup vs baseline: 1.1706x; 1.1706x over previous
#include <cuda_runtime.h>
#include <cuda_fp16.h>
#include <cstdint>

// ---------------- scratch (no cudaMalloc allowed) ----------------
__device__ __half g_h1h[256 * 1024 * 8];   // LSTM1 outputs as fp16, [B][S][8], 4MB

// ---------------- fast activations: MUFU.TANH based ----------------
__device__ __forceinline__ float tanhapx(float x) {
    float r; asm("tanh.approx.f32 %0, %1;" : "=f"(r) : "f"(x)); return r;
}
__device__ __forceinline__ __half2 u2h(unsigned u) {
    return *reinterpret_cast<__half2*>(&u);
}

__device__ __forceinline__ void lstm_upd(float& c, float& h,
                                         float gi, float gf, float gg, float go) {
    float ti = tanhapx(0.5f * gi);
    float tf = tanhapx(0.5f * gf);
    float tg = tanhapx(gg);
    float to = tanhapx(0.5f * go);
    float p  = fmaf(0.5f * ti, tg, 0.5f * tg);          // sig(i)*tanh(g)
    c = fmaf(0.5f * tf, c, fmaf(0.5f, c, p));           // sig(f)*c + p
    float tc = tanhapx(c);
    h = fmaf(0.5f * to, tc, 0.5f * tc);                 // sig(o)*tanh(c)
}

// =================================================================
// Kernel 1: LSTM1, half2 arithmetic. One thread per (b,s) sequence.
// Gates packed gate-major in half2 lanes: gates 0..31 = [i8 f8 g8 o8],
// acc[m] = gates (2m, 2m+1). W_ih/bias in registers; W_hh broadcast
// from smem as half2 (16 LDS.128 per step). c kept fp32 across steps.
// =================================================================
__global__ __launch_bounds__(256) void lstm1_kernel(
    const float* __restrict__ x,
    const float* __restrict__ W_ih1, const float* __restrict__ W_hh1,
    const float* __restrict__ b_ih1, const float* __restrict__ b_hh1)
{
    __shared__ __half2 sT[8][16];     // sT[e][m] = (W_hh1[2m][e], W_hh1[2m+1][e])
    __shared__ __half2 sI[16];        // W_ih pairs
    __shared__ __half2 sB[16];        // fused bias pairs
    int tid = threadIdx.x;
    if (tid < 32) {
        ((__half*)sI)[tid] = __float2half_rn(W_ih1[tid]);
        ((__half*)sB)[tid] = __float2half_rn(b_ih1[tid] + b_hh1[tid]);
    }
    {   // tid < 256 covers all (gate, e)
        int g = tid >> 3, e = tid & 7;
        ((__half*)&sT[e][0])[g] = __float2half_rn(W_hh1[g * 8 + e]);
    }
    __syncthreads();

    // hoist W_ih / bias into registers
    __half2 rI[16], rB[16];
#pragma unroll
    for (int m = 0; m < 16; m++) { rI[m] = sI[m]; rB[m] = sB[m]; }

    long n = (long)blockIdx.x * 256 + tid;
    const float4* xp = (const float4*)(x + n * 16);
    float4 xq[4];
    xq[0] = xp[0]; xq[1] = xp[1]; xq[2] = xp[2]; xq[3] = xp[3];
    float xv[16];
#pragma unroll
    for (int i = 0; i < 4; i++) {
        xv[4 * i + 0] = xq[i].x; xv[4 * i + 1] = xq[i].y;
        xv[4 * i + 2] = xq[i].z; xv[4 * i + 3] = xq[i].w;
    }

    float h[8], c[8];
#pragma unroll
    for (int d = 0; d < 8; d++) { h[d] = 0.f; c[d] = 0.f; }

#pragma unroll
    for (int t = 0; t < 16; t++) {
        __half2 xt2 = __float2half2_rn(xv[t]);
        __half2 acc[16];
#pragma unroll
        for (int m = 0; m < 16; m++)
            acc[m] = __hfma2(rI[m], xt2, rB[m]);
#pragma unroll
        for (int e = 0; e < 8; e++) {
            __half2 he2 = __float2half2_rn(h[e]);
            const __half2* T = sT[e];
#pragma unroll
            for (int m = 0; m < 16; m++)
                acc[m] = __hfma2(T[m], he2, acc[m]);
        }
        // unpack: i = acc[0..3], f = acc[4..7], g = acc[8..11], o = acc[12..15]
#pragma unroll
        for (int q = 0; q < 4; q++) {
            float2 fi = __half22float2(acc[q]);
            float2 ff = __half22float2(acc[4 + q]);
            float2 fg = __half22float2(acc[8 + q]);
            float2 fo = __half22float2(acc[12 + q]);
            lstm_upd(c[2 * q + 0], h[2 * q + 0], fi.x, ff.x, fg.x, fo.x);
            lstm_upd(c[2 * q + 1], h[2 * q + 1], fi.y, ff.y, fg.y, fo.y);
        }
    }

    __half2 p0 = __floats2half2_rn(h[0], h[1]);
    __half2 p1 = __floats2half2_rn(h[2], h[3]);
    __half2 p2 = __floats2half2_rn(h[4], h[5]);
    __half2 p3 = __floats2half2_rn(h[6], h[7]);
    uint4 u;
    u.x = *reinterpret_cast<uint32_t*>(&p0);
    u.y = *reinterpret_cast<uint32_t*>(&p1);
    u.z = *reinterpret_cast<uint32_t*>(&p2);
    u.w = *reinterpret_cast<uint32_t*>(&p3);
    *reinterpret_cast<uint4*>(g_h1h + n * 8) = u;
}

// =================================================================
// Kernel 2: LSTM2 — EXACT R10 design (best measured: 941 us).
// 128 CTAs x 512 threads, 2 batches/CTA. Thread j owns gate-row j,
// 68 half2 weight registers, HFMA2 chains flushed to fp32 every 32 k,
// gst float2 exchange, phase-B activations on threads t<256.
// =================================================================
__global__ void __launch_bounds__(512, 1) lstm2_kernel(
    const float* __restrict__ W_ih2, const float* __restrict__ W_hh2,
    const float* __restrict__ b_ih2, const float* __restrict__ b_hh2,
    const float* __restrict__ W1, const float* __restrict__ b1,
    const float* __restrict__ W2, const float* __restrict__ b2,
    float* __restrict__ out)
{
    __shared__ __half2 vecH[2][80];   // per batch: 68 used, pad to 80
    __shared__ float2  gst[512];
    __shared__ float   hb[256];
    __shared__ float   red[8];

    const int t  = threadIdx.x;
    const int j  = t;                 // gate row
    const int b0 = blockIdx.x * 2;

    // ---- pack this row's weights into 68 half2 registers ----
    __half2 wreg[68];
    {
        const float4* wi4 = (const float4*)(W_ih2 + j * 8);
#pragma unroll
        for (int q = 0; q < 2; q++) {
            float4 v = wi4[q];
            wreg[2 * q + 0] = __floats2half2_rn(v.x, v.y);
            wreg[2 * q + 1] = __floats2half2_rn(v.z, v.w);
        }
        const float4* wh4 = (const float4*)(W_hh2 + j * 128);
#pragma unroll
        for (int q = 0; q < 32; q++) {
            float4 v = wh4[q];
            wreg[4 + 2 * q + 0] = __floats2half2_rn(v.x, v.y);
            wreg[4 + 2 * q + 1] = __floats2half2_rn(v.z, v.w);
        }
    }
    const float bias = b_ih2[j] + b_hh2[j];

    // ---- init vec (h = 0), stage x_0, prefetch x_1 ----
    if (t < 160) ((float*)vecH)[t] = 0.f;
    __syncthreads();
    if (t < 16) {
        int b = t >> 3, k = t & 7;
        ((__half*)vecH[b])[k] = g_h1h[((long)(b0 + b) * 1024 + 0) * 8 + k];
    }
    float c_ = 0.f, h_ = 0.f;              // state for threads t<256 (d=t&127,b=t>>7)
    __half xr = __float2half_rn(0.f);      // x prefetch (threads 256..271)
    if (t >= 256 && t < 272) {
        int u = t - 256, b = u >> 3, k = u & 7;
        xr = g_h1h[((long)(b0 + b) * 1024 + 1) * 8 + k];
    }
    __syncthreads();

    const uint4* V0 = (const uint4*)(vecH[0]);   // uint4 = 4 half2 = 8 k
    const uint4* V1 = (const uint4*)(vecH[1]);
    const __half2 hz = __float2half2_rn(0.f);

    for (int step = 0; step < 1024; step++) {
        // ---- phase A: full-row dot products, 2 batches ----
        float a0 = bias, a1 = bias;
#pragma unroll
        for (int blk = 0; blk < 4; blk++) {       // q = 4*blk .. 4*blk+3 (32 k)
            __half2 sA0 = hz, sB0 = hz, sA1 = hz, sB1 = hz;
#pragma unroll
            for (int qq = 0; qq < 4; qq++) {
                int q = blk * 4 + qq;
                uint4 u0 = V0[q];
                uint4 u1 = V1[q];
                __half2 w0 = wreg[4 * q + 0], w1 = wreg[4 * q + 1];
                __half2 w2 = wreg[4 * q + 2], w3 = wreg[4 * q + 3];
                sA0 = __hfma2(w0, u2h(u0.x), sA0);
                sB0 = __hfma2(w1, u2h(u0.y), sB0);
                sA0 = __hfma2(w2, u2h(u0.z), sA0);
                sB0 = __hfma2(w3, u2h(u0.w), sB0);
                sA1 = __hfma2(w0, u2h(u1.x), sA1);
                sB1 = __hfma2(w1, u2h(u1.y), sB1);
                sA1 = __hfma2(w2, u2h(u1.z), sA1);
                sB1 = __hfma2(w3, u2h(u1.w), sB1);
            }
            float2 f0 = __half22float2(__hadd2(sA0, sB0));
            float2 f1 = __half22float2(__hadd2(sA1, sB1));
            a0 += f0.x; a0 += f0.y;
            a1 += f1.x; a1 += f1.y;
        }
        {   // tail: q = 16 (k 128..135)
            uint4 u0 = V0[16];
            uint4 u1 = V1[16];
            __half2 w0 = wreg[64], w1 = wreg[65], w2 = wreg[66], w3 = wreg[67];
            __half2 sA0 = __hfma2(w0, u2h(u0.x), hz);
            __half2 sB0 = __hfma2(w1, u2h(u0.y), hz);
            sA0 = __hfma2(w2, u2h(u0.z), sA0);
            sB0 = __hfma2(w3, u2h(u0.w), sB0);
            __half2 sA1 = __hfma2(w0, u2h(u1.x), hz);
            __half2 sB1 = __hfma2(w1, u2h(u1.y), hz);
            sA1 = __hfma2(w2, u2h(u1.z), sA1);
            sB1 = __hfma2(w3, u2h(u1.w), sB1);
            float2 f0 = __half22float2(__hadd2(sA0, sB0));
            float2 f1 = __half22float2(__hadd2(sA1, sB1));
            a0 += f0.x; a0 += f0.y;
            a1 += f1.x; a1 += f1.y;
        }
        gst[j] = make_float2(a0, a1);
        __syncthreads();

        // ---- phase B: activations + h/x staging ----
        if (t < 256) {
            int d = t & 127, b = t >> 7;
            float2 g_i = gst[d];
            float2 g_f = gst[128 + d];
            float2 g_g = gst[256 + d];
            float2 g_o = gst[384 + d];
            float gi = b ? g_i.y : g_i.x;
            float gf = b ? g_f.y : g_f.x;
            float gg = b ? g_g.y : g_g.x;
            float go = b ? g_o.y : g_o.x;
            float ti = tanhapx(0.5f * gi);
            float tf = tanhapx(0.5f * gf);
            float tg = tanhapx(gg);
            float to = tanhapx(0.5f * go);
            float pq = fmaf(0.5f * ti, tg, 0.5f * tg);
            c_ = fmaf(0.5f * tf, c_, fmaf(0.5f, c_, pq));
            float tc = tanhapx(c_);
            h_ = fmaf(0.5f * to, tc, 0.5f * tc);
            ((__half*)vecH[b])[8 + d] = __float2half_rn(h_);
        } else if (t < 272) {
            int u = t - 256, b = u >> 3, k = u & 7;
            ((__half*)vecH[b])[k] = xr;               // x_{step+1}
            if (step + 2 < 1024)
                xr = g_h1h[((long)(b0 + b) * 1024 + step + 2) * 8 + k];
        }
        __syncthreads();
    }

    // ---- epilogue: out[b] = (h @ W1^T + b1) @ W2^T + b2 ----
    if (t < 256) hb[(t >> 7) * 128 + (t & 127)] = h_;
    __syncthreads();
    if (t < 128) {
        int b = t >> 6, jj = t & 63;
        const float* hv  = hb + b * 128;
        const float* w1r = W1 + jj * 128;
        float m_ = b1[jj];
#pragma unroll
        for (int k = 0; k < 128; k++) m_ = fmaf(w1r[k], hv[k], m_);
        float pr = m_ * W2[jj];
#pragma unroll
        for (int off = 16; off; off >>= 1)
            pr += __shfl_xor_sync(0xffffffff, pr, off);
        if ((t & 31) == 0) red[t >> 5] = pr;
    }
    __syncthreads();
    if (t < 2)
        out[b0 + t] = red[t * 2] + red[t * 2 + 1] + b2[0];
}

// =================================================================
extern "C" void kernel_launch(void* const* d_in, const int* in_sizes, int n_in,
                              void* d_out, int out_size) {
    const float* x     = (const float*)d_in[0];
    // d_in[1] = data (unused)
    const float* W_ih1 = (const float*)d_in[2];
    const float* W_hh1 = (const float*)d_in[3];
    const float* b_ih1 = (const float*)d_in[4];
    const float* b_hh1 = (const float*)d_in[5];
    const float* W_ih2 = (const float*)d_in[6];
    const float* W_hh2 = (const float*)d_in[7];
    const float* b_ih2 = (const float*)d_in[8];
    const float* b_hh2 = (const float*)d_in[9];
    const float* W1    = (const float*)d_in[10];
    const float* b1    = (const float*)d_in[11];
    const float* W2    = (const float*)d_in[12];
    const float* b2    = (const float*)d_in[13];
    float* out = (float*)d_out;

    lstm1_kernel<<<1024, 256>>>(x, W_ih1, W_hh1, b_ih1, b_hh1);

    lstm2_kernel<<<128, 512>>>(W_ih2, W_hh2, b_ih2, b_hh2,
                               W1, b1, W2, b2, out);
}